// round 3
// baseline (speedup 1.0000x reference)
#include <cuda_runtime.h>

#define B_ 4
#define N_ 2048
#define DIN 128
#define H_ 4
#define HD_ 32
#define BH (B_*H_)
#define NEG_SLOPE 0.2f

// Scratch (device globals: no allocation allowed in kernel_launch)
__device__ float g_h[B_*N_*DIN];     // projected features, [b*N+n][head*32+d]
__device__ float g_Wt[DIN*DIN];      // W transposed: [k][o]
__device__ float g_ei[BH*N_];        // [(b*H+h)*N + n]
__device__ float g_ej[BH*N_];
__device__ float g_maxej[BH*N_];     // masked row-max of ej per (b,h,i)

// ---------------------------------------------------------------------------
// Kernel 0: transpose W so the GEMM reads it coalesced
// ---------------------------------------------------------------------------
__global__ void k_transpose(const float* __restrict__ W) {
    int k = blockIdx.x, o = threadIdx.x;
    g_Wt[k*DIN + o] = W[o*DIN + k];
}

// ---------------------------------------------------------------------------
// Kernel 1: h = x @ W^T  (+ fused ei/ej = per-head dot with a1/a2)
// 128 threads per block, 32 x-rows per block, thread owns one output column.
// ---------------------------------------------------------------------------
__global__ void __launch_bounds__(128) k_gemm(const float* __restrict__ x,
                                              const float* __restrict__ a) {
    __shared__ float xs[32][DIN];
    int row0 = blockIdx.x * 32;
    int tid = threadIdx.x;

    const float4* xsrc = (const float4*)(x + (size_t)row0 * DIN);
    float4* xdst = (float4*)&xs[0][0];
    #pragma unroll
    for (int t = tid; t < 32*DIN/4; t += 128) xdst[t] = xsrc[t];
    __syncthreads();

    int o = tid;
    float acc[32];
    #pragma unroll
    for (int r = 0; r < 32; r++) acc[r] = 0.f;

    for (int k = 0; k < DIN; k++) {
        float w = g_Wt[k*DIN + o];
        #pragma unroll
        for (int r = 0; r < 32; r++) acc[r] += xs[r][k] * w;
    }

    // warp w covers o in [32w, 32w+32) == exactly head w (H=4, HD=32)
    int head = tid >> 5, d = tid & 31;
    float a1 = a[head*2*HD_ + d];
    float a2 = a[head*2*HD_ + HD_ + d];

    #pragma unroll
    for (int r = 0; r < 32; r++) {
        int bn = row0 + r;
        g_h[(size_t)bn*DIN + o] = acc[r];
        float p1 = acc[r] * a1;
        float p2 = acc[r] * a2;
        #pragma unroll
        for (int off = 16; off > 0; off >>= 1) {
            p1 += __shfl_xor_sync(0xffffffffu, p1, off);
            p2 += __shfl_xor_sync(0xffffffffu, p2, off);
        }
        if (d == 0) {
            int b = bn / N_, n = bn % N_;
            g_ei[(b*H_ + head)*N_ + n] = p1;
            g_ej[(b*H_ + head)*N_ + n] = p2;
        }
    }
}

// ---------------------------------------------------------------------------
// Kernel 2: masked row-max of ej.
// leaky is monotone, so row softmax max = leaky(ei_i + max_{adj[i,j]!=0} ej_j).
// One block per i-row; each block computes all 16 (b,h) maxima at once so the
// adj row is read once.
// ---------------------------------------------------------------------------
__global__ void __launch_bounds__(256) k_maxej(const int* __restrict__ adj) {
    int i = blockIdx.x;
    int tid = threadIdx.x;
    const float NEG_INF = __int_as_float(0xff800000);

    float m[BH];
    #pragma unroll
    for (int q = 0; q < BH; q++) m[q] = NEG_INF;

    for (int j = tid; j < N_; j += 256) {
        if (adj[(size_t)i*N_ + j] != 0) {
            #pragma unroll
            for (int q = 0; q < BH; q++) m[q] = fmaxf(m[q], g_ej[q*N_ + j]);
        }
    }

    __shared__ float red[8][BH];
    #pragma unroll
    for (int q = 0; q < BH; q++) {
        float v = m[q];
        #pragma unroll
        for (int off = 16; off > 0; off >>= 1)
            v = fmaxf(v, __shfl_xor_sync(0xffffffffu, v, off));
        m[q] = v;
    }
    if ((tid & 31) == 0) {
        #pragma unroll
        for (int q = 0; q < BH; q++) red[tid >> 5][q] = m[q];
    }
    __syncthreads();
    if (tid < BH) {
        float v = red[0][tid];
        #pragma unroll
        for (int w2 = 1; w2 < 8; w2++) v = fmaxf(v, red[w2][tid]);
        g_maxej[tid*N_ + i] = v;
    }
}

// ---------------------------------------------------------------------------
// Kernel 3: fused masked softmax + aggregation.
// grid = (16 (b,h), 64 i-tiles). Block: 256 threads = 8 warps, 32 i per block,
// each warp owns 4 i-rows with register accumulators (lane = d).
// Single pass: row max is precomputed, so p = exp(s - m) directly; normalize
// by the lane-reduced sum at the end.
// ---------------------------------------------------------------------------
__global__ void __launch_bounds__(256) k_attn(const int* __restrict__ adj,
                                              float* __restrict__ out) {
    __shared__ float ejs[N_];          // 8 KB
    __shared__ float hs[256][HD_];     // 32 KB j-chunk of h
    __shared__ float ps[8][4][32];     // 4 KB attn weights per warp

    int bh = blockIdx.x;
    int b = bh >> 2, head = bh & 3;
    int tid = threadIdx.x, w = tid >> 5, lane = tid & 31;

    {   // stage all ej for this (b,h)
        const float4* src = (const float4*)(g_ej + bh*N_);
        float4* dst = (float4*)ejs;
        #pragma unroll
        for (int t = tid; t < N_/4; t += 256) dst[t] = src[t];
    }

    int i0 = blockIdx.y*32 + w*4;
    float eiv[4], mv[4], acc[4], lsum[4];
    #pragma unroll
    for (int ii = 0; ii < 4; ii++) {
        int i = i0 + ii;
        eiv[ii] = g_ei[bh*N_ + i];
        float s = eiv[ii] + g_maxej[bh*N_ + i];
        mv[ii] = (s > 0.f) ? s : NEG_SLOPE * s;
        acc[ii] = 0.f;
        lsum[ii] = 0.f;
    }

    for (int j0 = 0; j0 < N_; j0 += 256) {
        __syncthreads();   // covers ejs staging + previous chunk's reads of hs
        {   // stage h[b, j0:j0+256, head, :] -> hs
            const float* base = g_h + ((size_t)(b*N_ + j0))*DIN + head*HD_;
            #pragma unroll
            for (int t = tid; t < 256*8; t += 256) {
                int jj = t >> 3, dq = t & 7;
                *(float4*)&hs[jj][dq*4] =
                    *(const float4*)(base + (size_t)jj*DIN + dq*4);
            }
        }
        __syncthreads();

        #pragma unroll 1
        for (int js = 0; js < 256; js += 32) {
            int j = j0 + js + lane;
            float ejv = ejs[js + j0 + lane];
            #pragma unroll
            for (int ii = 0; ii < 4; ii++) {
                float s = eiv[ii] + ejv;
                s = (s > 0.f) ? s : NEG_SLOPE * s;
                float p = 0.f;
                if (adj[(size_t)(i0 + ii)*N_ + j] != 0)
                    p = __expf(s - mv[ii]);
                lsum[ii] += p;
                ps[w][ii][lane] = p;
            }
            __syncwarp();
            #pragma unroll
            for (int k = 0; k < 32; k += 4) {
                float4 p0 = *(const float4*)&ps[w][0][k];
                float4 p1 = *(const float4*)&ps[w][1][k];
                float4 p2 = *(const float4*)&ps[w][2][k];
                float4 p3 = *(const float4*)&ps[w][3][k];
                float hv;
                hv = hs[js+k+0][lane];
                acc[0] += p0.x*hv; acc[1] += p1.x*hv; acc[2] += p2.x*hv; acc[3] += p3.x*hv;
                hv = hs[js+k+1][lane];
                acc[0] += p0.y*hv; acc[1] += p1.y*hv; acc[2] += p2.y*hv; acc[3] += p3.y*hv;
                hv = hs[js+k+2][lane];
                acc[0] += p0.z*hv; acc[1] += p1.z*hv; acc[2] += p2.z*hv; acc[3] += p3.z*hv;
                hv = hs[js+k+3][lane];
                acc[0] += p0.w*hv; acc[1] += p1.w*hv; acc[2] += p2.w*hv; acc[3] += p3.w*hv;
            }
            __syncwarp();   // before ps is overwritten by next group
        }
    }

    #pragma unroll
    for (int ii = 0; ii < 4; ii++) {
        float l = lsum[ii];
        #pragma unroll
        for (int off = 16; off > 0; off >>= 1)
            l += __shfl_xor_sync(0xffffffffu, l, off);
        out[((size_t)(b*N_ + i0 + ii))*DIN + head*HD_ + lane] =
            acc[ii] * __fdividef(1.f, l);
    }
}

// ---------------------------------------------------------------------------
extern "C" void kernel_launch(void* const* d_in, const int* in_sizes, int n_in,
                              void* d_out, int out_size) {
    const float* x   = (const float*)d_in[0];
    const int*   adj = (const int*)  d_in[1];
    const float* W   = (const float*)d_in[2];
    const float* a   = (const float*)d_in[3];
    float* out = (float*)d_out;

    k_transpose<<<DIN, DIN>>>(W);
    k_gemm<<<(B_*N_)/32, 128>>>(x, a);
    k_maxej<<<N_, 256>>>(adj);
    dim3 grid(BH, N_/32);
    k_attn<<<grid, 256>>>(adj, out);
}